// round 8
// baseline (speedup 1.0000x reference)
#include <cuda_runtime.h>
#include <cuda_bf16.h>

// ---------------------------------------------------------------------------
// HiLo attention, b=8, dim=256, H=W=64, WS=2, 4+4 heads, head_dim=32
// Round 8: operands pre-split to bf16 hi/lo once; GEMMs are pure
// cp.async (double-buffered) + ldmatrix + HMMA bf16x3 pipelines.
// Attention kernels emit bf16 hi/lo outputs for the projection GEMMs.
// ---------------------------------------------------------------------------

#define BB 8
#define CDIM 256
#define NTOK 4096          // 64*64 tokens per batch
#define MPOOL 1024         // 32*32 pooled tokens per batch
#define ATTN_SCALE 0.17677669529663687f   // 32^-0.5

typedef unsigned long long u64;
typedef unsigned int u32;

// fp32 intermediates (attention inputs)
__device__ float g_qkv [BB * NTOK * 384];   // hifi qkv  [b][t][s*128+head*32+d]
__device__ float g_ql  [BB * NTOK * 128];   // lofi q    [b][t][head*32+d]
__device__ float g_kvl [BB * MPOOL * 256];  // lofi kv   [b][m][s*128+head*32+d]

// bf16 hi/lo operand tensors
__device__ __nv_bfloat16 g_xhi [BB * CDIM * NTOK];   // x       [b][c][t] K-major
__device__ __nv_bfloat16 g_xlo [BB * CDIM * NTOK];
__device__ __nv_bfloat16 g_phi [BB * CDIM * MPOOL];  // pooled  [b][c][m] K-major
__device__ __nv_bfloat16 g_plo [BB * CDIM * MPOOL];
__device__ __nv_bfloat16 g_whi [229376];             // all weights, see offsets
__device__ __nv_bfloat16 g_wlo [229376];
__device__ __nv_bfloat16 g_ohhi[BB * NTOK * 128];    // hifi attn out [b][t][c]
__device__ __nv_bfloat16 g_ohlo[BB * NTOK * 128];
__device__ __nv_bfloat16 g_olhi[BB * NTOK * 128];    // lofi attn out
__device__ __nv_bfloat16 g_ollo[BB * NTOK * 128];

// weight segment offsets in g_whi/g_wlo
#define WOFF_HQKV   0        // 256*384
#define WOFF_LQ     98304    // 256*128
#define WOFF_LKV    131072   // 256*256
#define WOFF_HPROJ  196608   // 128*128
#define WOFF_LPROJ  212992   // 128*128

// ---- helpers ---------------------------------------------------------------
__device__ __forceinline__ void mma_bf16(
    float* c, const u32* a, u32 b0, u32 b1)
{
    asm volatile(
        "mma.sync.aligned.m16n8k16.row.col.f32.bf16.bf16.f32 "
        "{%0,%1,%2,%3}, {%4,%5,%6,%7}, {%8,%9}, {%0,%1,%2,%3};\n"
        : "+f"(c[0]), "+f"(c[1]), "+f"(c[2]), "+f"(c[3])
        : "r"(a[0]), "r"(a[1]), "r"(a[2]), "r"(a[3]), "r"(b0), "r"(b1));
}
// split two floats into packed bf16x2 hi + residual bf16x2 lo (mem order x0,x1)
__device__ __forceinline__ void bf16_split2(float x0, float x1, u32& hi, u32& lo)
{
    asm("cvt.rn.bf16x2.f32 %0, %1, %2;" : "=r"(hi) : "f"(x1), "f"(x0));
    float h0 = __uint_as_float(hi << 16);
    float h1 = __uint_as_float(hi & 0xffff0000u);
    asm("cvt.rn.bf16x2.f32 %0, %1, %2;" : "=r"(lo) : "f"(x1 - h1), "f"(x0 - h0));
}
__device__ __forceinline__ u32 s2u(const void* p) {
    return (u32)__cvta_generic_to_shared(p);
}
__device__ __forceinline__ void ldsm_x4_t(u32& r0, u32& r1, u32& r2, u32& r3, u32 addr)
{
    asm volatile("ldmatrix.sync.aligned.m8n8.x4.trans.shared.b16 "
                 "{%0,%1,%2,%3}, [%4];"
                 : "=r"(r0), "=r"(r1), "=r"(r2), "=r"(r3) : "r"(addr));
}
__device__ __forceinline__ void ldsm_x4(u32& r0, u32& r1, u32& r2, u32& r3, u32 addr)
{
    asm volatile("ldmatrix.sync.aligned.m8n8.x4.shared.b16 "
                 "{%0,%1,%2,%3}, [%4];"
                 : "=r"(r0), "=r"(r1), "=r"(r2), "=r"(r3) : "r"(addr));
}
__device__ __forceinline__ void cp_cg(u32 dst, const void* src)
{
    asm volatile("cp.async.cg.shared.global [%0], [%1], 16;\n"
                 :: "r"(dst), "l"(src));
}
#define CP_COMMIT() asm volatile("cp.async.commit_group;\n")

// ---------------------------------------------------------------------------
// convert x -> bf16 hi/lo and fused 2x2 avg pool -> bf16 hi/lo
// grid: BB*CDIM blocks of 256 threads; one block per [b][c] row of 4096.
// ---------------------------------------------------------------------------
__global__ __launch_bounds__(256) void convert_x_pool(const float* __restrict__ x)
{
    const int bc = blockIdx.x;
    const float* xp = x + (long)bc * 4096;
    __nv_bfloat16* xh = g_xhi + (long)bc * 4096;
    __nv_bfloat16* xl = g_xlo + (long)bc * 4096;
#pragma unroll
    for (int p = 0; p < 4; p++) {
        const int i = threadIdx.x * 4 + p * 1024;
        float4 v = *(const float4*)&xp[i];
        u32 h01, l01, h23, l23;
        bf16_split2(v.x, v.y, h01, l01);
        bf16_split2(v.z, v.w, h23, l23);
        *(u32*)&xh[i] = h01; *(u32*)&xh[i + 2] = h23;
        *(u32*)&xl[i] = l01; *(u32*)&xl[i + 2] = l23;
    }
    __nv_bfloat16* ph = g_phi + (long)bc * 1024;
    __nv_bfloat16* pl = g_plo + (long)bc * 1024;
#pragma unroll
    for (int p = 0; p < 2; p++) {
        const int m = threadIdx.x * 2 + p * 512;       // even -> wg even
        const int hg = m >> 5, wg = m & 31;
        const float* r0 = xp + hg * 128 + wg * 2;
        float4 a = *(const float4*)&r0[0];
        float4 b = *(const float4*)&r0[64];
        float p0 = 0.25f * (a.x + a.y + b.x + b.y);
        float p1 = 0.25f * (a.z + a.w + b.z + b.w);
        u32 h, l;
        bf16_split2(p0, p1, h, l);
        *(u32*)&ph[m] = h;
        *(u32*)&pl[m] = l;
    }
}

// ---------------------------------------------------------------------------
// convert all 5 weight matrices into g_whi/g_wlo (229376 elems)
// grid: 224 blocks x 256 thr x 4 elems
// ---------------------------------------------------------------------------
__global__ __launch_bounds__(256) void convert_w(
    const float* __restrict__ w0, const float* __restrict__ w1,
    const float* __restrict__ w2, const float* __restrict__ w3,
    const float* __restrict__ w4)
{
    const long idx = ((long)blockIdx.x * 256 + threadIdx.x) * 4;
    const float* src; long off;
    if (idx < WOFF_LQ)         { src = w0; off = 0; }
    else if (idx < WOFF_LKV)   { src = w1; off = WOFF_LQ; }
    else if (idx < WOFF_HPROJ) { src = w2; off = WOFF_LKV; }
    else if (idx < WOFF_LPROJ) { src = w3; off = WOFF_HPROJ; }
    else                       { src = w4; off = WOFF_LPROJ; }
    float4 v = *(const float4*)&src[idx - off];
    u32 h01, l01, h23, l23;
    bf16_split2(v.x, v.y, h01, l01);
    bf16_split2(v.z, v.w, h23, l23);
    *(u32*)&g_whi[idx] = h01; *(u32*)&g_whi[idx + 2] = h23;
    *(u32*)&g_wlo[idx] = l01; *(u32*)&g_wlo[idx + 2] = l23;
}

// ---------------------------------------------------------------------------
// Pipelined bf16x3 GEMM, A K-major bf16 hi/lo: C[b][m][n] = sum_k A[k][m]W[k][n]
// K=256, BM=128, BN=64, BK=32, 256 thr (8 warps 4m x 2n), double-buffered
// cp.async. Dynamic smem: A 2x2x32x136 + W 2x2x32x72 bf16 = 53248 B.
// ---------------------------------------------------------------------------
#define XT_SMEM 53248
__global__ __launch_bounds__(256, 2) void gemm_xt_pipe(
    const __nv_bfloat16* __restrict__ Ahi, const __nv_bfloat16* __restrict__ Alo,
    long aBatch, int woff,
    float* __restrict__ Cout, long cBatch, int M, int N)
{
    extern __shared__ char smraw[];
    const u32 sbase = s2u(smraw);
#define SA_(buf,hl,k,m) (sbase + (((((buf)*2+(hl))*32)+(k))*136 + (m))*2)
#define SW_(buf,hl,k,n) (sbase + 34816 + (((((buf)*2+(hl))*32)+(k))*72 + (n))*2)

    const int tid = threadIdx.x;
    const int wid = tid >> 5;
    const int lane = tid & 31;
    const int m0 = blockIdx.x * 128;
    const int n0 = blockIdx.y * 64;
    const int wm = (wid & 3) * 32;
    const int wn = (wid >> 2) * 32;
    const __nv_bfloat16* Ah = Ahi + (long)blockIdx.z * aBatch + m0;
    const __nv_bfloat16* Al = Alo + (long)blockIdx.z * aBatch + m0;
    const __nv_bfloat16* Wh = g_whi + woff + n0;
    const __nv_bfloat16* Wl = g_wlo + woff + n0;
    float* Cb = Cout + (long)blockIdx.z * cBatch;

    const int l7 = lane & 7;
    const int a_koff = l7 + ((lane & 16) ? 8 : 0);
    const int a_moff = (lane & 8) ? 8 : 0;
    const int b_koff = l7 + ((lane & 8) ? 8 : 0);
    const int b_noff = (lane & 16) ? 8 : 0;

    // per-thread cp.async coordinates
    const int ar0 = tid >> 4,          ac0 = (tid & 15) * 8;
    const int ar1 = (tid + 256) >> 4,  ac1 = ((tid + 256) & 15) * 8;
    const int wr = tid >> 3,           wc = (tid & 7) * 8;

    float acc[2][4][4];
#pragma unroll
    for (int i = 0; i < 2; i++)
#pragma unroll
        for (int j = 0; j < 4; j++)
#pragma unroll
            for (int c = 0; c < 4; c++) acc[i][j][c] = 0.f;

    // issue chunk 0
    {
        cp_cg(SA_(0, 0, ar0, ac0), Ah + (long)ar0 * M + ac0);
        cp_cg(SA_(0, 1, ar0, ac0), Al + (long)ar0 * M + ac0);
        cp_cg(SA_(0, 0, ar1, ac1), Ah + (long)ar1 * M + ac1);
        cp_cg(SA_(0, 1, ar1, ac1), Al + (long)ar1 * M + ac1);
        cp_cg(SW_(0, 0, wr, wc), Wh + (long)wr * N + wc);
        cp_cg(SW_(0, 1, wr, wc), Wl + (long)wr * N + wc);
        CP_COMMIT();
    }

#pragma unroll
    for (int it = 0; it < 8; it++) {
        if (it < 7) {
            const int nb = (it + 1) & 1;
            const long kb = (long)(it + 1) * 32;
            cp_cg(SA_(nb, 0, ar0, ac0), Ah + (kb + ar0) * M + ac0);
            cp_cg(SA_(nb, 1, ar0, ac0), Al + (kb + ar0) * M + ac0);
            cp_cg(SA_(nb, 0, ar1, ac1), Ah + (kb + ar1) * M + ac1);
            cp_cg(SA_(nb, 1, ar1, ac1), Al + (kb + ar1) * M + ac1);
            cp_cg(SW_(nb, 0, wr, wc), Wh + (kb + wr) * N + wc);
            cp_cg(SW_(nb, 1, wr, wc), Wl + (kb + wr) * N + wc);
            CP_COMMIT();
            asm volatile("cp.async.wait_group 1;\n");
        } else {
            asm volatile("cp.async.wait_group 0;\n");
        }
        __syncthreads();

        const int buf = it & 1;
#pragma unroll
        for (int ks = 0; ks < 2; ks++) {
            const int kk = ks * 16;
            u32 ahi[2][4], alo[2][4];
#pragma unroll
            for (int i = 0; i < 2; i++) {
                const int mb = wm + i * 16;
                ldsm_x4_t(ahi[i][0], ahi[i][1], ahi[i][2], ahi[i][3],
                          SA_(buf, 0, kk + a_koff, mb + a_moff));
                ldsm_x4_t(alo[i][0], alo[i][1], alo[i][2], alo[i][3],
                          SA_(buf, 1, kk + a_koff, mb + a_moff));
            }
            u32 bhi[4][2], blo[4][2];
#pragma unroll
            for (int np = 0; np < 2; np++) {
                const int nb2 = wn + np * 16;
                u32 r0, r1, r2, r3;
                ldsm_x4_t(r0, r1, r2, r3, SW_(buf, 0, kk + b_koff, nb2 + b_noff));
                bhi[2 * np][0] = r0; bhi[2 * np][1] = r1;
                bhi[2 * np + 1][0] = r2; bhi[2 * np + 1][1] = r3;
                ldsm_x4_t(r0, r1, r2, r3, SW_(buf, 1, kk + b_koff, nb2 + b_noff));
                blo[2 * np][0] = r0; blo[2 * np][1] = r1;
                blo[2 * np + 1][0] = r2; blo[2 * np + 1][1] = r3;
            }
#pragma unroll
            for (int i = 0; i < 2; i++)
#pragma unroll
                for (int j = 0; j < 4; j++) {
                    mma_bf16(acc[i][j], ahi[i], bhi[j][0], bhi[j][1]);
                    mma_bf16(acc[i][j], alo[i], bhi[j][0], bhi[j][1]);
                    mma_bf16(acc[i][j], ahi[i], blo[j][0], blo[j][1]);
                }
        }
        __syncthreads();
    }

    const int g = lane >> 2, tg = lane & 3;
#pragma unroll
    for (int i = 0; i < 2; i++)
#pragma unroll
        for (int j = 0; j < 4; j++) {
            const int row = m0 + wm + i * 16 + g;
            const int col = n0 + wn + j * 8 + 2 * tg;
            *(float2*)&Cb[(long)row * N + col] =
                make_float2(acc[i][j][0], acc[i][j][1]);
            *(float2*)&Cb[(long)(row + 8) * N + col] =
                make_float2(acc[i][j][2], acc[i][j][3]);
        }
#undef SA_
#undef SW_
}

// ---------------------------------------------------------------------------
// Pipelined bf16x3 projection GEMM, K=128, A row-major bf16 hi/lo [M][128].
// out[(b*256+coff+n)*4096+m] = bias[n] + A@W. Dyn smem:
// A 2x2x128x40 + W 2x2x32x72 bf16 = 59392 B.
// ---------------------------------------------------------------------------
#define PJ_SMEM 59392
__global__ __launch_bounds__(256, 2) void gemm_proj_pipe(
    const __nv_bfloat16* __restrict__ Ahi, const __nv_bfloat16* __restrict__ Alo,
    long aBatch, int woff,
    const float* __restrict__ bias,
    float* __restrict__ out, int coff)
{
    extern __shared__ char smraw[];
    const u32 sbase = s2u(smraw);
#define SA_(buf,hl,m,k) (sbase + (((((buf)*2+(hl))*128)+(m))*40 + (k))*2)
#define SW_(buf,hl,k,n) (sbase + 40960 + (((((buf)*2+(hl))*32)+(k))*72 + (n))*2)

    const int tid = threadIdx.x;
    const int wid = tid >> 5;
    const int lane = tid & 31;
    const int m0 = blockIdx.x * 128;
    const int n0 = blockIdx.y * 64;
    const int wm = (wid & 3) * 32;
    const int wn = (wid >> 2) * 32;
    const __nv_bfloat16* Ah = Ahi + (long)blockIdx.z * aBatch + (long)m0 * 128;
    const __nv_bfloat16* Al = Alo + (long)blockIdx.z * aBatch + (long)m0 * 128;
    const __nv_bfloat16* Wh = g_whi + woff + n0;
    const __nv_bfloat16* Wl = g_wlo + woff + n0;

    const int l7 = lane & 7;
    const int a_moff = l7 + ((lane & 8) ? 8 : 0);
    const int a_koff = (lane & 16) ? 8 : 0;
    const int b_koff = l7 + ((lane & 8) ? 8 : 0);
    const int b_noff = (lane & 16) ? 8 : 0;

    const int ar0 = tid >> 2,          ac0 = (tid & 3) * 8;
    const int ar1 = (tid + 256) >> 2,  ac1 = ((tid + 256) & 3) * 8;
    const int wr = tid >> 3,           wc = (tid & 7) * 8;

    float acc[2][4][4];
#pragma unroll
    for (int i = 0; i < 2; i++)
#pragma unroll
        for (int j = 0; j < 4; j++)
#pragma unroll
            for (int c = 0; c < 4; c++) acc[i][j][c] = 0.f;

    {
        cp_cg(SA_(0, 0, ar0, ac0), Ah + (long)ar0 * 128 + ac0);
        cp_cg(SA_(0, 1, ar0, ac0), Al + (long)ar0 * 128 + ac0);
        cp_cg(SA_(0, 0, ar1, ac1), Ah + (long)ar1 * 128 + ac1);
        cp_cg(SA_(0, 1, ar1, ac1), Al + (long)ar1 * 128 + ac1);
        cp_cg(SW_(0, 0, wr, wc), Wh + (long)wr * 128 + wc);
        cp_cg(SW_(0, 1, wr, wc), Wl + (long)wr * 128 + wc);
        CP_COMMIT();
    }

#pragma unroll
    for (int it = 0; it < 4; it++) {
        if (it < 3) {
            const int nb = (it + 1) & 1;
            const long kb = (long)(it + 1) * 32;
            cp_cg(SA_(nb, 0, ar0, ac0), Ah + (long)ar0 * 128 + kb + ac0);
            cp_cg(SA_(nb, 1, ar0, ac0), Al + (long)ar0 * 128 + kb + ac0);
            cp_cg(SA_(nb, 0, ar1, ac1), Ah + (long)ar1 * 128 + kb + ac1);
            cp_cg(SA_(nb, 1, ar1, ac1), Al + (long)ar1 * 128 + kb + ac1);
            cp_cg(SW_(nb, 0, wr, wc), Wh + (kb + wr) * 128 + wc);
            cp_cg(SW_(nb, 1, wr, wc), Wl + (kb + wr) * 128 + wc);
            CP_COMMIT();
            asm volatile("cp.async.wait_group 1;\n");
        } else {
            asm volatile("cp.async.wait_group 0;\n");
        }
        __syncthreads();

        const int buf = it & 1;
#pragma unroll
        for (int ks = 0; ks < 2; ks++) {
            const int kk = ks * 16;
            u32 ahi[2][4], alo[2][4];
#pragma unroll
            for (int i = 0; i < 2; i++) {
                const int mb = wm + i * 16;
                ldsm_x4(ahi[i][0], ahi[i][1], ahi[i][2], ahi[i][3],
                        SA_(buf, 0, mb + a_moff, kk + a_koff));
                ldsm_x4(alo[i][0], alo[i][1], alo[i][2], alo[i][3],
                        SA_(buf, 1, mb + a_moff, kk + a_koff));
            }
            u32 bhi[4][2], blo[4][2];
#pragma unroll
            for (int np = 0; np < 2; np++) {
                const int nb2 = wn + np * 16;
                u32 r0, r1, r2, r3;
                ldsm_x4_t(r0, r1, r2, r3, SW_(buf, 0, kk + b_koff, nb2 + b_noff));
                bhi[2 * np][0] = r0; bhi[2 * np][1] = r1;
                bhi[2 * np + 1][0] = r2; bhi[2 * np + 1][1] = r3;
                ldsm_x4_t(r0, r1, r2, r3, SW_(buf, 1, kk + b_koff, nb2 + b_noff));
                blo[2 * np][0] = r0; blo[2 * np][1] = r1;
                blo[2 * np + 1][0] = r2; blo[2 * np + 1][1] = r3;
            }
#pragma unroll
            for (int i = 0; i < 2; i++)
#pragma unroll
                for (int j = 0; j < 4; j++) {
                    mma_bf16(acc[i][j], ahi[i], bhi[j][0], bhi[j][1]);
                    mma_bf16(acc[i][j], alo[i], bhi[j][0], bhi[j][1]);
                    mma_bf16(acc[i][j], ahi[i], blo[j][0], blo[j][1]);
                }
        }
        __syncthreads();
    }

    const int g = lane >> 2, tg = lane & 3;
    float* ob = out + ((long)blockIdx.z * 256 + coff) * 4096;
#pragma unroll
    for (int j = 0; j < 4; j++) {
        const int nl = n0 + wn + j * 8 + 2 * tg;
        const float bv0 = bias[nl];
        const float bv1 = bias[nl + 1];
#pragma unroll
        for (int i = 0; i < 2; i++) {
            const int m = m0 + wm + i * 16 + g;
            ob[(long)nl * 4096 + m]           = acc[i][j][0] + bv0;
            ob[(long)(nl + 1) * 4096 + m]     = acc[i][j][1] + bv1;
            ob[(long)nl * 4096 + m + 8]       = acc[i][j][2] + bv0;
            ob[(long)(nl + 1) * 4096 + m + 8] = acc[i][j][3] + bv1;
        }
    }
#undef SA_
#undef SW_
}

// ---------------------------------------------------------------------------
// hifi window attention: one warp per (b, window, head); emits bf16 hi/lo.
// ---------------------------------------------------------------------------
__global__ __launch_bounds__(256) void hifi_attn()
{
    const int wid = (blockIdx.x * blockDim.x + threadIdx.x) >> 5;
    const int lane = threadIdx.x & 31;
    const int head = wid & 3;
    const int win = (wid >> 2) & 1023;
    const int b = wid >> 12;
    const int hg = win >> 5, wgc = win & 31;

    float q[4], k[4], v[4];
    int t[4];
#pragma unroll
    for (int i = 0; i < 4; i++) {
        const int r = 2 * hg + (i >> 1);
        const int c = 2 * wgc + (i & 1);
        t[i] = r * 64 + c;
        const float* base = g_qkv + (long)(b * NTOK + t[i]) * 384 + head * 32 + lane;
        q[i] = base[0];
        k[i] = base[128];
        v[i] = base[256];
    }
    float s[4][4];
#pragma unroll
    for (int i = 0; i < 4; i++)
#pragma unroll
        for (int j = 0; j < 4; j++) {
            float p = q[i] * k[j];
#pragma unroll
            for (int off = 16; off; off >>= 1)
                p += __shfl_xor_sync(0xffffffffu, p, off);
            s[i][j] = p * ATTN_SCALE;
        }
#pragma unroll
    for (int i = 0; i < 4; i++) {
        float mx = fmaxf(fmaxf(s[i][0], s[i][1]), fmaxf(s[i][2], s[i][3]));
        float e0 = __expf(s[i][0] - mx);
        float e1 = __expf(s[i][1] - mx);
        float e2 = __expf(s[i][2] - mx);
        float e3 = __expf(s[i][3] - mx);
        float inv = 1.0f / (e0 + e1 + e2 + e3);
        float o = (e0 * v[0] + e1 * v[1] + e2 * v[2] + e3 * v[3]) * inv;
        const long idx = (long)(b * NTOK + t[i]) * 128 + head * 32 + lane;
        __nv_bfloat16 h = __float2bfloat16(o);
        g_ohhi[idx] = h;
        g_ohlo[idx] = __float2bfloat16(o - __bfloat162float(h));
    }
}

// ---------------------------------------------------------------------------
// lofi flash attention on tensor cores (bf16x3, m16n8k16); emits bf16 hi/lo.
// ---------------------------------------------------------------------------
__global__ __launch_bounds__(256, 2) void lofi_attn_mma()
{
    __shared__ __nv_bfloat16 sKhi[64][40];
    __shared__ __nv_bfloat16 sKlo[64][40];
    __shared__ __nv_bfloat16 sVhi[32][72];
    __shared__ __nv_bfloat16 sVlo[32][72];

    const int tid = threadIdx.x;
    const int lane = tid & 31;
    const int warp = tid >> 5;
    const int g = lane >> 2;
    const int tg = lane & 3;
    const int bh = blockIdx.y;
    const int b = bh >> 2, head = bh & 3;
    const int qrow0 = blockIdx.x * 128 + warp * 16;

    const float* qbase = g_ql + ((long)(b * NTOK + qrow0)) * 128 + head * 32;
    u32 qa_hi[2][4], qa_lo[2][4];
#pragma unroll
    for (int kt = 0; kt < 2; kt++) {
        float2 f0 = *(const float2*)&qbase[(long)g * 128 + kt * 16 + 2 * tg];
        float2 f1 = *(const float2*)&qbase[(long)(g + 8) * 128 + kt * 16 + 2 * tg];
        float2 f2 = *(const float2*)&qbase[(long)g * 128 + kt * 16 + 8 + 2 * tg];
        float2 f3 = *(const float2*)&qbase[(long)(g + 8) * 128 + kt * 16 + 8 + 2 * tg];
        bf16_split2(f0.x * ATTN_SCALE, f0.y * ATTN_SCALE, qa_hi[kt][0], qa_lo[kt][0]);
        bf16_split2(f1.x * ATTN_SCALE, f1.y * ATTN_SCALE, qa_hi[kt][1], qa_lo[kt][1]);
        bf16_split2(f2.x * ATTN_SCALE, f2.y * ATTN_SCALE, qa_hi[kt][2], qa_lo[kt][2]);
        bf16_split2(f3.x * ATTN_SCALE, f3.y * ATTN_SCALE, qa_hi[kt][3], qa_lo[kt][3]);
    }

    float od[4][4];
#pragma unroll
    for (int dt = 0; dt < 4; dt++)
#pragma unroll
        for (int c = 0; c < 4; c++) od[dt][c] = 0.f;
    float mrow[2] = {-1e30f, -1e30f};
    float lrow[2] = {0.f, 0.f};

    const float* kvb = g_kvl + (long)b * MPOOL * 256 + head * 32;

    for (int j0 = 0; j0 < MPOOL; j0 += 64) {
        __syncthreads();
#pragma unroll
        for (int p = 0; p < 2; p++) {
            const int idx = tid + 256 * p;
            const int r = idx >> 3;
            const int c4 = (idx & 7) * 4;
            const float* row = &kvb[(long)(j0 + r) * 256];
            float4 kf = *(const float4*)&row[c4];
            u32 h0, l0, h1, l1;
            bf16_split2(kf.x, kf.y, h0, l0);
            bf16_split2(kf.z, kf.w, h1, l1);
            *(u32*)&sKhi[r][c4]     = h0;
            *(u32*)&sKhi[r][c4 + 2] = h1;
            *(u32*)&sKlo[r][c4]     = l0;
            *(u32*)&sKlo[r][c4 + 2] = l1;
            float4 vf = *(const float4*)&row[128 + c4];
#pragma unroll
            for (int i = 0; i < 4; i++) {
                float v = (&vf.x)[i];
                __nv_bfloat16 vh = __float2bfloat16(v);
                sVhi[c4 + i][r] = vh;
                sVlo[c4 + i][r] = __float2bfloat16(v - __bfloat162float(vh));
            }
        }
        __syncthreads();

        float s[8][4];
#pragma unroll
        for (int nt = 0; nt < 8; nt++) {
            float c[4] = {0.f, 0.f, 0.f, 0.f};
            const int kv = nt * 8 + g;
#pragma unroll
            for (int kt = 0; kt < 2; kt++) {
                const int kk = kt * 16;
                u32 bh0 = *(const u32*)&sKhi[kv][kk + 2 * tg];
                u32 bh1 = *(const u32*)&sKhi[kv][kk + 8 + 2 * tg];
                u32 bl0 = *(const u32*)&sKlo[kv][kk + 2 * tg];
                u32 bl1 = *(const u32*)&sKlo[kv][kk + 8 + 2 * tg];
                mma_bf16(c, qa_hi[kt], bh0, bh1);
                mma_bf16(c, qa_lo[kt], bh0, bh1);
                mma_bf16(c, qa_hi[kt], bl0, bl1);
            }
            s[nt][0] = c[0]; s[nt][1] = c[1]; s[nt][2] = c[2]; s[nt][3] = c[3];
        }

        float mx0 = s[0][0], mx1 = s[0][2];
#pragma unroll
        for (int nt = 0; nt < 8; nt++) {
            mx0 = fmaxf(mx0, fmaxf(s[nt][0], s[nt][1]));
            mx1 = fmaxf(mx1, fmaxf(s[nt][2], s[nt][3]));
        }
        mx0 = fmaxf(mx0, __shfl_xor_sync(0xffffffffu, mx0, 1));
        mx0 = fmaxf(mx0, __shfl_xor_sync(0xffffffffu, mx0, 2));
        mx1 = fmaxf(mx1, __shfl_xor_sync(0xffffffffu, mx1, 1));
        mx1 = fmaxf(mx1, __shfl_xor_sync(0xffffffffu, mx1, 2));

        const float mn0 = fmaxf(mrow[0], mx0);
        const float mn1 = fmaxf(mrow[1], mx1);
        const float sf0 = __expf(mrow[0] - mn0);
        const float sf1 = __expf(mrow[1] - mn1);
        mrow[0] = mn0; mrow[1] = mn1;
        lrow[0] *= sf0; lrow[1] *= sf1;
#pragma unroll
        for (int dt = 0; dt < 4; dt++) {
            od[dt][0] *= sf0; od[dt][1] *= sf0;
            od[dt][2] *= sf1; od[dt][3] *= sf1;
        }
#pragma unroll
        for (int nt = 0; nt < 8; nt++) {
            s[nt][0] = __expf(s[nt][0] - mn0);
            s[nt][1] = __expf(s[nt][1] - mn0);
            s[nt][2] = __expf(s[nt][2] - mn1);
            s[nt][3] = __expf(s[nt][3] - mn1);
            lrow[0] += s[nt][0] + s[nt][1];
            lrow[1] += s[nt][2] + s[nt][3];
        }

#pragma unroll
        for (int kt2 = 0; kt2 < 4; kt2++) {
            u32 pa_hi[4], pa_lo[4];
            bf16_split2(s[2 * kt2][0],     s[2 * kt2][1],     pa_hi[0], pa_lo[0]);
            bf16_split2(s[2 * kt2][2],     s[2 * kt2][3],     pa_hi[1], pa_lo[1]);
            bf16_split2(s[2 * kt2 + 1][0], s[2 * kt2 + 1][1], pa_hi[2], pa_lo[2]);
            bf16_split2(s[2 * kt2 + 1][2], s[2 * kt2 + 1][3], pa_hi[3], pa_lo[3]);
            const int kv0 = kt2 * 16;
#pragma unroll
            for (int dt = 0; dt < 4; dt++) {
                const int d = dt * 8 + g;
                u32 vb_h0 = *(const u32*)&sVhi[d][kv0 + 2 * tg];
                u32 vb_h1 = *(const u32*)&sVhi[d][kv0 + 8 + 2 * tg];
                u32 vb_l0 = *(const u32*)&sVlo[d][kv0 + 2 * tg];
                u32 vb_l1 = *(const u32*)&sVlo[d][kv0 + 8 + 2 * tg];
                mma_bf16(od[dt], pa_hi, vb_h0, vb_h1);
                mma_bf16(od[dt], pa_lo, vb_h0, vb_h1);
                mma_bf16(od[dt], pa_hi, vb_l0, vb_l1);
            }
        }
    }

    lrow[0] += __shfl_xor_sync(0xffffffffu, lrow[0], 1);
    lrow[0] += __shfl_xor_sync(0xffffffffu, lrow[0], 2);
    lrow[1] += __shfl_xor_sync(0xffffffffu, lrow[1], 1);
    lrow[1] += __shfl_xor_sync(0xffffffffu, lrow[1], 2);
    const float inv0 = 1.0f / lrow[0];
    const float inv1 = 1.0f / lrow[1];

    const long obase = ((long)(b * NTOK + qrow0)) * 128 + head * 32;
#pragma unroll
    for (int dt = 0; dt < 4; dt++) {
        const int col = dt * 8 + 2 * tg;
        u32 h, l;
        bf16_split2(od[dt][0] * inv0, od[dt][1] * inv0, h, l);
        *(u32*)&g_olhi[obase + (long)g * 128 + col] = h;
        *(u32*)&g_ollo[obase + (long)g * 128 + col] = l;
        bf16_split2(od[dt][2] * inv1, od[dt][3] * inv1, h, l);
        *(u32*)&g_olhi[obase + (long)(g + 8) * 128 + col] = h;
        *(u32*)&g_ollo[obase + (long)(g + 8) * 128 + col] = l;
    }
}

// ---------------------------------------------------------------------------
extern "C" void kernel_launch(void* const* d_in, const int* in_sizes, int n_in,
                              void* d_out, int out_size)
{
    const float* x        = (const float*)d_in[0];
    const float* l_q_w    = (const float*)d_in[1];
    const float* l_kv_w   = (const float*)d_in[2];
    const float* l_proj_w = (const float*)d_in[3];
    const float* l_proj_b = (const float*)d_in[4];
    const float* h_qkv_w  = (const float*)d_in[5];
    const float* h_proj_w = (const float*)d_in[6];
    const float* h_proj_b = (const float*)d_in[7];
    float* out = (float*)d_out;

    cudaFuncSetAttribute(gemm_xt_pipe,
                         cudaFuncAttributeMaxDynamicSharedMemorySize, XT_SMEM);
    cudaFuncSetAttribute(gemm_proj_pipe,
                         cudaFuncAttributeMaxDynamicSharedMemorySize, PJ_SMEM);

    float *qkv, *ql, *kvl;
    __nv_bfloat16 *xhi, *xlo, *phi, *plo, *ohhi, *ohlo, *olhi, *ollo;
    cudaGetSymbolAddress((void**)&qkv,  g_qkv);
    cudaGetSymbolAddress((void**)&ql,   g_ql);
    cudaGetSymbolAddress((void**)&kvl,  g_kvl);
    cudaGetSymbolAddress((void**)&xhi,  g_xhi);
    cudaGetSymbolAddress((void**)&xlo,  g_xlo);
    cudaGetSymbolAddress((void**)&phi,  g_phi);
    cudaGetSymbolAddress((void**)&plo,  g_plo);
    cudaGetSymbolAddress((void**)&ohhi, g_ohhi);
    cudaGetSymbolAddress((void**)&ohlo, g_ohlo);
    cudaGetSymbolAddress((void**)&olhi, g_olhi);
    cudaGetSymbolAddress((void**)&ollo, g_ollo);

    // operand conversion
    convert_w<<<224, 256>>>(h_qkv_w, l_q_w, l_kv_w, h_proj_w, l_proj_w);
    convert_x_pool<<<BB * CDIM, 256>>>(x);

    // hifi qkv: x^T @ h_qkv_w -> [b][4096][384] fp32
    gemm_xt_pipe<<<dim3(32, 6, 8), 256, XT_SMEM>>>(
        xhi, xlo, (long)CDIM * NTOK, WOFF_HQKV, qkv, (long)NTOK * 384, NTOK, 384);
    // lofi q: x^T @ l_q_w -> [b][4096][128] fp32
    gemm_xt_pipe<<<dim3(32, 2, 8), 256, XT_SMEM>>>(
        xhi, xlo, (long)CDIM * NTOK, WOFF_LQ, ql, (long)NTOK * 128, NTOK, 128);
    // lofi kv: pooled^T @ l_kv_w -> [b][1024][256] fp32
    gemm_xt_pipe<<<dim3(8, 4, 8), 256, XT_SMEM>>>(
        phi, plo, (long)CDIM * MPOOL, WOFF_LKV, kvl, (long)MPOOL * 256, MPOOL, 256);

    // attention (emit bf16 hi/lo)
    hifi_attn<<<4096, 256>>>();
    lofi_attn_mma<<<dim3(32, 32), 256>>>();

    // projections, fused concat+transpose into output
    gemm_proj_pipe<<<dim3(32, 2, 8), 256, PJ_SMEM>>>(
        ohhi, ohlo, (long)NTOK * 128, WOFF_HPROJ, h_proj_b, out, 0);
    gemm_proj_pipe<<<dim3(32, 2, 8), 256, PJ_SMEM>>>(
        olhi, ollo, (long)NTOK * 128, WOFF_LPROJ, l_proj_b, out, 128);
}

// round 9
// speedup vs baseline: 1.0025x; 1.0025x over previous
#include <cuda_runtime.h>
#include <cuda_bf16.h>

// ---------------------------------------------------------------------------
// HiLo attention, b=8, dim=256, H=W=64, WS=2, 4+4 heads, head_dim=32
// Round 9: GEMM pipelines deepened to 3-stage cp.async with a single
// __syncthreads per k-chunk (2-chunk lookahead). Math identical to R8.
// ---------------------------------------------------------------------------

#define BB 8
#define CDIM 256
#define NTOK 4096          // 64*64 tokens per batch
#define MPOOL 1024         // 32*32 pooled tokens per batch
#define ATTN_SCALE 0.17677669529663687f   // 32^-0.5

typedef unsigned long long u64;
typedef unsigned int u32;

// fp32 intermediates (attention inputs)
__device__ float g_qkv [BB * NTOK * 384];   // hifi qkv  [b][t][s*128+head*32+d]
__device__ float g_ql  [BB * NTOK * 128];   // lofi q    [b][t][head*32+d]
__device__ float g_kvl [BB * MPOOL * 256];  // lofi kv   [b][m][s*128+head*32+d]

// bf16 hi/lo operand tensors
__device__ __nv_bfloat16 g_xhi [BB * CDIM * NTOK];   // x       [b][c][t] K-major
__device__ __nv_bfloat16 g_xlo [BB * CDIM * NTOK];
__device__ __nv_bfloat16 g_phi [BB * CDIM * MPOOL];  // pooled  [b][c][m] K-major
__device__ __nv_bfloat16 g_plo [BB * CDIM * MPOOL];
__device__ __nv_bfloat16 g_whi [229376];             // all weights, see offsets
__device__ __nv_bfloat16 g_wlo [229376];
__device__ __nv_bfloat16 g_ohhi[BB * NTOK * 128];    // hifi attn out [b][t][c]
__device__ __nv_bfloat16 g_ohlo[BB * NTOK * 128];
__device__ __nv_bfloat16 g_olhi[BB * NTOK * 128];    // lofi attn out
__device__ __nv_bfloat16 g_ollo[BB * NTOK * 128];

// weight segment offsets in g_whi/g_wlo
#define WOFF_HQKV   0        // 256*384
#define WOFF_LQ     98304    // 256*128
#define WOFF_LKV    131072   // 256*256
#define WOFF_HPROJ  196608   // 128*128
#define WOFF_LPROJ  212992   // 128*128

// ---- helpers ---------------------------------------------------------------
__device__ __forceinline__ void mma_bf16(
    float* c, const u32* a, u32 b0, u32 b1)
{
    asm volatile(
        "mma.sync.aligned.m16n8k16.row.col.f32.bf16.bf16.f32 "
        "{%0,%1,%2,%3}, {%4,%5,%6,%7}, {%8,%9}, {%0,%1,%2,%3};\n"
        : "+f"(c[0]), "+f"(c[1]), "+f"(c[2]), "+f"(c[3])
        : "r"(a[0]), "r"(a[1]), "r"(a[2]), "r"(a[3]), "r"(b0), "r"(b1));
}
// split two floats into packed bf16x2 hi + residual bf16x2 lo (mem order x0,x1)
__device__ __forceinline__ void bf16_split2(float x0, float x1, u32& hi, u32& lo)
{
    asm("cvt.rn.bf16x2.f32 %0, %1, %2;" : "=r"(hi) : "f"(x1), "f"(x0));
    float h0 = __uint_as_float(hi << 16);
    float h1 = __uint_as_float(hi & 0xffff0000u);
    asm("cvt.rn.bf16x2.f32 %0, %1, %2;" : "=r"(lo) : "f"(x1 - h1), "f"(x0 - h0));
}
__device__ __forceinline__ u32 s2u(const void* p) {
    return (u32)__cvta_generic_to_shared(p);
}
__device__ __forceinline__ void ldsm_x4_t(u32& r0, u32& r1, u32& r2, u32& r3, u32 addr)
{
    asm volatile("ldmatrix.sync.aligned.m8n8.x4.trans.shared.b16 "
                 "{%0,%1,%2,%3}, [%4];"
                 : "=r"(r0), "=r"(r1), "=r"(r2), "=r"(r3) : "r"(addr));
}
__device__ __forceinline__ void ldsm_x4(u32& r0, u32& r1, u32& r2, u32& r3, u32 addr)
{
    asm volatile("ldmatrix.sync.aligned.m8n8.x4.shared.b16 "
                 "{%0,%1,%2,%3}, [%4];"
                 : "=r"(r0), "=r"(r1), "=r"(r2), "=r"(r3) : "r"(addr));
}
__device__ __forceinline__ void cp_cg(u32 dst, const void* src)
{
    asm volatile("cp.async.cg.shared.global [%0], [%1], 16;\n"
                 :: "r"(dst), "l"(src));
}
#define CP_COMMIT() asm volatile("cp.async.commit_group;\n")

// ---------------------------------------------------------------------------
// convert x -> bf16 hi/lo and fused 2x2 avg pool -> bf16 hi/lo
// ---------------------------------------------------------------------------
__global__ __launch_bounds__(256) void convert_x_pool(const float* __restrict__ x)
{
    const int bc = blockIdx.x;
    const float* xp = x + (long)bc * 4096;
    __nv_bfloat16* xh = g_xhi + (long)bc * 4096;
    __nv_bfloat16* xl = g_xlo + (long)bc * 4096;
#pragma unroll
    for (int p = 0; p < 4; p++) {
        const int i = threadIdx.x * 4 + p * 1024;
        float4 v = *(const float4*)&xp[i];
        u32 h01, l01, h23, l23;
        bf16_split2(v.x, v.y, h01, l01);
        bf16_split2(v.z, v.w, h23, l23);
        *(u32*)&xh[i] = h01; *(u32*)&xh[i + 2] = h23;
        *(u32*)&xl[i] = l01; *(u32*)&xl[i + 2] = l23;
    }
    __nv_bfloat16* ph = g_phi + (long)bc * 1024;
    __nv_bfloat16* pl = g_plo + (long)bc * 1024;
#pragma unroll
    for (int p = 0; p < 2; p++) {
        const int m = threadIdx.x * 2 + p * 512;
        const int hg = m >> 5, wg = m & 31;
        const float* r0 = xp + hg * 128 + wg * 2;
        float4 a = *(const float4*)&r0[0];
        float4 b = *(const float4*)&r0[64];
        float p0 = 0.25f * (a.x + a.y + b.x + b.y);
        float p1 = 0.25f * (a.z + a.w + b.z + b.w);
        u32 h, l;
        bf16_split2(p0, p1, h, l);
        *(u32*)&ph[m] = h;
        *(u32*)&pl[m] = l;
    }
}

// ---------------------------------------------------------------------------
// convert all 5 weight matrices into g_whi/g_wlo (229376 elems)
// ---------------------------------------------------------------------------
__global__ __launch_bounds__(256) void convert_w(
    const float* __restrict__ w0, const float* __restrict__ w1,
    const float* __restrict__ w2, const float* __restrict__ w3,
    const float* __restrict__ w4)
{
    const long idx = ((long)blockIdx.x * 256 + threadIdx.x) * 4;
    const float* src; long off;
    if (idx < WOFF_LQ)         { src = w0; off = 0; }
    else if (idx < WOFF_LKV)   { src = w1; off = WOFF_LQ; }
    else if (idx < WOFF_HPROJ) { src = w2; off = WOFF_LKV; }
    else if (idx < WOFF_LPROJ) { src = w3; off = WOFF_HPROJ; }
    else                       { src = w4; off = WOFF_LPROJ; }
    float4 v = *(const float4*)&src[idx - off];
    u32 h01, l01, h23, l23;
    bf16_split2(v.x, v.y, h01, l01);
    bf16_split2(v.z, v.w, h23, l23);
    *(u32*)&g_whi[idx] = h01; *(u32*)&g_whi[idx + 2] = h23;
    *(u32*)&g_wlo[idx] = l01; *(u32*)&g_wlo[idx + 2] = l23;
}

// ---------------------------------------------------------------------------
// 3-stage pipelined bf16x3 GEMM, A K-major bf16 hi/lo.
// K=256, BM=128, BN=64, BK=32, 256 thr (8 warps 4m x 2n).
// Smem: 3 stages x (A 2x32x136 + W 2x32x72) bf16 = 79872 B.
// ---------------------------------------------------------------------------
#define XT_SMEM 79872
__global__ __launch_bounds__(256, 2) void gemm_xt_pipe(
    const __nv_bfloat16* __restrict__ Ahi, const __nv_bfloat16* __restrict__ Alo,
    long aBatch, int woff,
    float* __restrict__ Cout, long cBatch, int M, int N)
{
    extern __shared__ char smraw[];
    const u32 sbase = s2u(smraw);
#define SA_(st,hl,k,m) (sbase + (((((st)*2+(hl))*32)+(k))*136 + (m))*2)
#define SW_(st,hl,k,n) (sbase + 52224 + (((((st)*2+(hl))*32)+(k))*72 + (n))*2)

    const int tid = threadIdx.x;
    const int wid = tid >> 5;
    const int lane = tid & 31;
    const int m0 = blockIdx.x * 128;
    const int n0 = blockIdx.y * 64;
    const int wm = (wid & 3) * 32;
    const int wn = (wid >> 2) * 32;
    const __nv_bfloat16* Ah = Ahi + (long)blockIdx.z * aBatch + m0;
    const __nv_bfloat16* Al = Alo + (long)blockIdx.z * aBatch + m0;
    const __nv_bfloat16* Wh = g_whi + woff + n0;
    const __nv_bfloat16* Wl = g_wlo + woff + n0;
    float* Cb = Cout + (long)blockIdx.z * cBatch;

    const int l7 = lane & 7;
    const int a_koff = l7 + ((lane & 16) ? 8 : 0);
    const int a_moff = (lane & 8) ? 8 : 0;
    const int b_koff = l7 + ((lane & 8) ? 8 : 0);
    const int b_noff = (lane & 16) ? 8 : 0;

    const int ar0 = tid >> 4,          ac0 = (tid & 15) * 8;
    const int ar1 = (tid + 256) >> 4,  ac1 = ((tid + 256) & 15) * 8;
    const int wr = tid >> 3,           wc = (tid & 7) * 8;

    auto issue_chunk = [&](int st, int chunk) {
        const long kb = (long)chunk * 32;
        cp_cg(SA_(st, 0, ar0, ac0), Ah + (kb + ar0) * M + ac0);
        cp_cg(SA_(st, 1, ar0, ac0), Al + (kb + ar0) * M + ac0);
        cp_cg(SA_(st, 0, ar1, ac1), Ah + (kb + ar1) * M + ac1);
        cp_cg(SA_(st, 1, ar1, ac1), Al + (kb + ar1) * M + ac1);
        cp_cg(SW_(st, 0, wr, wc), Wh + (kb + wr) * N + wc);
        cp_cg(SW_(st, 1, wr, wc), Wl + (kb + wr) * N + wc);
        CP_COMMIT();
    };

    float acc[2][4][4];
#pragma unroll
    for (int i = 0; i < 2; i++)
#pragma unroll
        for (int j = 0; j < 4; j++)
#pragma unroll
            for (int c = 0; c < 4; c++) acc[i][j][c] = 0.f;

    issue_chunk(0, 0);
    issue_chunk(1, 1);

#pragma unroll
    for (int it = 0; it < 8; it++) {
        if (it < 7) asm volatile("cp.async.wait_group 1;\n");
        else        asm volatile("cp.async.wait_group 0;\n");
        __syncthreads();
        if (it + 2 < 8) issue_chunk((it + 2) % 3, it + 2);

        const int st = it % 3;
#pragma unroll
        for (int ks = 0; ks < 2; ks++) {
            const int kk = ks * 16;
            u32 ahi[2][4], alo[2][4];
#pragma unroll
            for (int i = 0; i < 2; i++) {
                const int mb = wm + i * 16;
                ldsm_x4_t(ahi[i][0], ahi[i][1], ahi[i][2], ahi[i][3],
                          SA_(st, 0, kk + a_koff, mb + a_moff));
                ldsm_x4_t(alo[i][0], alo[i][1], alo[i][2], alo[i][3],
                          SA_(st, 1, kk + a_koff, mb + a_moff));
            }
            u32 bhi[4][2], blo[4][2];
#pragma unroll
            for (int np = 0; np < 2; np++) {
                const int nb2 = wn + np * 16;
                u32 r0, r1, r2, r3;
                ldsm_x4_t(r0, r1, r2, r3, SW_(st, 0, kk + b_koff, nb2 + b_noff));
                bhi[2 * np][0] = r0; bhi[2 * np][1] = r1;
                bhi[2 * np + 1][0] = r2; bhi[2 * np + 1][1] = r3;
                ldsm_x4_t(r0, r1, r2, r3, SW_(st, 1, kk + b_koff, nb2 + b_noff));
                blo[2 * np][0] = r0; blo[2 * np][1] = r1;
                blo[2 * np + 1][0] = r2; blo[2 * np + 1][1] = r3;
            }
#pragma unroll
            for (int i = 0; i < 2; i++)
#pragma unroll
                for (int j = 0; j < 4; j++) {
                    mma_bf16(acc[i][j], ahi[i], bhi[j][0], bhi[j][1]);
                    mma_bf16(acc[i][j], alo[i], bhi[j][0], bhi[j][1]);
                    mma_bf16(acc[i][j], ahi[i], blo[j][0], blo[j][1]);
                }
        }
    }

    const int g = lane >> 2, tg = lane & 3;
#pragma unroll
    for (int i = 0; i < 2; i++)
#pragma unroll
        for (int j = 0; j < 4; j++) {
            const int row = m0 + wm + i * 16 + g;
            const int col = n0 + wn + j * 8 + 2 * tg;
            *(float2*)&Cb[(long)row * N + col] =
                make_float2(acc[i][j][0], acc[i][j][1]);
            *(float2*)&Cb[(long)(row + 8) * N + col] =
                make_float2(acc[i][j][2], acc[i][j][3]);
        }
#undef SA_
#undef SW_
}

// ---------------------------------------------------------------------------
// 3-stage pipelined bf16x3 projection GEMM, K=128, A row-major [M][128].
// out[(b*256+coff+n)*4096+m] = bias[n] + A@W.
// Smem: 3 x (A 2x128x40 + W 2x32x72) bf16 = 89088 B.
// ---------------------------------------------------------------------------
#define PJ_SMEM 89088
__global__ __launch_bounds__(256, 2) void gemm_proj_pipe(
    const __nv_bfloat16* __restrict__ Ahi, const __nv_bfloat16* __restrict__ Alo,
    long aBatch, int woff,
    const float* __restrict__ bias,
    float* __restrict__ out, int coff)
{
    extern __shared__ char smraw[];
    const u32 sbase = s2u(smraw);
#define SA_(st,hl,m,k) (sbase + (((((st)*2+(hl))*128)+(m))*40 + (k))*2)
#define SW_(st,hl,k,n) (sbase + 61440 + (((((st)*2+(hl))*32)+(k))*72 + (n))*2)

    const int tid = threadIdx.x;
    const int wid = tid >> 5;
    const int lane = tid & 31;
    const int m0 = blockIdx.x * 128;
    const int n0 = blockIdx.y * 64;
    const int wm = (wid & 3) * 32;
    const int wn = (wid >> 2) * 32;
    const __nv_bfloat16* Ah = Ahi + (long)blockIdx.z * aBatch + (long)m0 * 128;
    const __nv_bfloat16* Al = Alo + (long)blockIdx.z * aBatch + (long)m0 * 128;
    const __nv_bfloat16* Wh = g_whi + woff + n0;
    const __nv_bfloat16* Wl = g_wlo + woff + n0;

    const int l7 = lane & 7;
    const int a_moff = l7 + ((lane & 8) ? 8 : 0);
    const int a_koff = (lane & 16) ? 8 : 0;
    const int b_koff = l7 + ((lane & 8) ? 8 : 0);
    const int b_noff = (lane & 16) ? 8 : 0;

    const int ar0 = tid >> 2,          ac0 = (tid & 3) * 8;
    const int ar1 = (tid + 256) >> 2,  ac1 = ((tid + 256) & 3) * 8;
    const int wr = tid >> 3,           wc = (tid & 7) * 8;

    auto issue_chunk = [&](int st, int chunk) {
        const long kb = (long)chunk * 32;
        cp_cg(SA_(st, 0, ar0, ac0), Ah + (long)ar0 * 128 + kb + ac0);
        cp_cg(SA_(st, 1, ar0, ac0), Al + (long)ar0 * 128 + kb + ac0);
        cp_cg(SA_(st, 0, ar1, ac1), Ah + (long)ar1 * 128 + kb + ac1);
        cp_cg(SA_(st, 1, ar1, ac1), Al + (long)ar1 * 128 + kb + ac1);
        cp_cg(SW_(st, 0, wr, wc), Wh + (kb + wr) * 128 + wc);
        cp_cg(SW_(st, 1, wr, wc), Wl + (kb + wr) * 128 + wc);
        CP_COMMIT();
    };

    float acc[2][4][4];
#pragma unroll
    for (int i = 0; i < 2; i++)
#pragma unroll
        for (int j = 0; j < 4; j++)
#pragma unroll
            for (int c = 0; c < 4; c++) acc[i][j][c] = 0.f;

    issue_chunk(0, 0);
    issue_chunk(1, 1);

#pragma unroll
    for (int it = 0; it < 4; it++) {
        if (it < 3) asm volatile("cp.async.wait_group 1;\n");
        else        asm volatile("cp.async.wait_group 0;\n");
        __syncthreads();
        if (it + 2 < 4) issue_chunk((it + 2) % 3, it + 2);

        const int st = it % 3;
#pragma unroll
        for (int ks = 0; ks < 2; ks++) {
            const int kk = ks * 16;
            u32 ahi[2][4], alo[2][4];
#pragma unroll
            for (int i = 0; i < 2; i++) {
                const int mb = wm + i * 16;
                ldsm_x4(ahi[i][0], ahi[i][1], ahi[i][2], ahi[i][3],
                        SA_(st, 0, mb + a_moff, kk + a_koff));
                ldsm_x4(alo[i][0], alo[i][1], alo[i][2], alo[i][3],
                        SA_(st, 1, mb + a_moff, kk + a_koff));
            }
            u32 bhi[4][2], blo[4][2];
#pragma unroll
            for (int np = 0; np < 2; np++) {
                const int nb2 = wn + np * 16;
                u32 r0, r1, r2, r3;
                ldsm_x4_t(r0, r1, r2, r3, SW_(st, 0, kk + b_koff, nb2 + b_noff));
                bhi[2 * np][0] = r0; bhi[2 * np][1] = r1;
                bhi[2 * np + 1][0] = r2; bhi[2 * np + 1][1] = r3;
                ldsm_x4_t(r0, r1, r2, r3, SW_(st, 1, kk + b_koff, nb2 + b_noff));
                blo[2 * np][0] = r0; blo[2 * np][1] = r1;
                blo[2 * np + 1][0] = r2; blo[2 * np + 1][1] = r3;
            }
#pragma unroll
            for (int i = 0; i < 2; i++)
#pragma unroll
                for (int j = 0; j < 4; j++) {
                    mma_bf16(acc[i][j], ahi[i], bhi[j][0], bhi[j][1]);
                    mma_bf16(acc[i][j], alo[i], bhi[j][0], bhi[j][1]);
                    mma_bf16(acc[i][j], ahi[i], blo[j][0], blo[j][1]);
                }
        }
    }

    const int g = lane >> 2, tg = lane & 3;
    float* ob = out + ((long)blockIdx.z * 256 + coff) * 4096;
#pragma unroll
    for (int j = 0; j < 4; j++) {
        const int nl = n0 + wn + j * 8 + 2 * tg;
        const float bv0 = bias[nl];
        const float bv1 = bias[nl + 1];
#pragma unroll
        for (int i = 0; i < 2; i++) {
            const int m = m0 + wm + i * 16 + g;
            ob[(long)nl * 4096 + m]           = acc[i][j][0] + bv0;
            ob[(long)(nl + 1) * 4096 + m]     = acc[i][j][1] + bv1;
            ob[(long)nl * 4096 + m + 8]       = acc[i][j][2] + bv0;
            ob[(long)(nl + 1) * 4096 + m + 8] = acc[i][j][3] + bv1;
        }
    }
#undef SA_
#undef SW_
}

// ---------------------------------------------------------------------------
// hifi window attention: one warp per (b, window, head); emits bf16 hi/lo.
// ---------------------------------------------------------------------------
__global__ __launch_bounds__(256) void hifi_attn()
{
    const int wid = (blockIdx.x * blockDim.x + threadIdx.x) >> 5;
    const int lane = threadIdx.x & 31;
    const int head = wid & 3;
    const int win = (wid >> 2) & 1023;
    const int b = wid >> 12;
    const int hg = win >> 5, wgc = win & 31;

    float q[4], k[4], v[4];
    int t[4];
#pragma unroll
    for (int i = 0; i < 4; i++) {
        const int r = 2 * hg + (i >> 1);
        const int c = 2 * wgc + (i & 1);
        t[i] = r * 64 + c;
        const float* base = g_qkv + (long)(b * NTOK + t[i]) * 384 + head * 32 + lane;
        q[i] = base[0];
        k[i] = base[128];
        v[i] = base[256];
    }
    float s[4][4];
#pragma unroll
    for (int i = 0; i < 4; i++)
#pragma unroll
        for (int j = 0; j < 4; j++) {
            float p = q[i] * k[j];
#pragma unroll
            for (int off = 16; off; off >>= 1)
                p += __shfl_xor_sync(0xffffffffu, p, off);
            s[i][j] = p * ATTN_SCALE;
        }
#pragma unroll
    for (int i = 0; i < 4; i++) {
        float mx = fmaxf(fmaxf(s[i][0], s[i][1]), fmaxf(s[i][2], s[i][3]));
        float e0 = __expf(s[i][0] - mx);
        float e1 = __expf(s[i][1] - mx);
        float e2 = __expf(s[i][2] - mx);
        float e3 = __expf(s[i][3] - mx);
        float inv = 1.0f / (e0 + e1 + e2 + e3);
        float o = (e0 * v[0] + e1 * v[1] + e2 * v[2] + e3 * v[3]) * inv;
        const long idx = (long)(b * NTOK + t[i]) * 128 + head * 32 + lane;
        __nv_bfloat16 h = __float2bfloat16(o);
        g_ohhi[idx] = h;
        g_ohlo[idx] = __float2bfloat16(o - __bfloat162float(h));
    }
}

// ---------------------------------------------------------------------------
// lofi flash attention on tensor cores (bf16x3, m16n8k16); emits bf16 hi/lo.
// ---------------------------------------------------------------------------
__global__ __launch_bounds__(256, 2) void lofi_attn_mma()
{
    __shared__ __nv_bfloat16 sKhi[64][40];
    __shared__ __nv_bfloat16 sKlo[64][40];
    __shared__ __nv_bfloat16 sVhi[32][72];
    __shared__ __nv_bfloat16 sVlo[32][72];

    const int tid = threadIdx.x;
    const int lane = tid & 31;
    const int warp = tid >> 5;
    const int g = lane >> 2;
    const int tg = lane & 3;
    const int bh = blockIdx.y;
    const int b = bh >> 2, head = bh & 3;
    const int qrow0 = blockIdx.x * 128 + warp * 16;

    const float* qbase = g_ql + ((long)(b * NTOK + qrow0)) * 128 + head * 32;
    u32 qa_hi[2][4], qa_lo[2][4];
#pragma unroll
    for (int kt = 0; kt < 2; kt++) {
        float2 f0 = *(const float2*)&qbase[(long)g * 128 + kt * 16 + 2 * tg];
        float2 f1 = *(const float2*)&qbase[(long)(g + 8) * 128 + kt * 16 + 2 * tg];
        float2 f2 = *(const float2*)&qbase[(long)g * 128 + kt * 16 + 8 + 2 * tg];
        float2 f3 = *(const float2*)&qbase[(long)(g + 8) * 128 + kt * 16 + 8 + 2 * tg];
        bf16_split2(f0.x * ATTN_SCALE, f0.y * ATTN_SCALE, qa_hi[kt][0], qa_lo[kt][0]);
        bf16_split2(f1.x * ATTN_SCALE, f1.y * ATTN_SCALE, qa_hi[kt][1], qa_lo[kt][1]);
        bf16_split2(f2.x * ATTN_SCALE, f2.y * ATTN_SCALE, qa_hi[kt][2], qa_lo[kt][2]);
        bf16_split2(f3.x * ATTN_SCALE, f3.y * ATTN_SCALE, qa_hi[kt][3], qa_lo[kt][3]);
    }

    float od[4][4];
#pragma unroll
    for (int dt = 0; dt < 4; dt++)
#pragma unroll
        for (int c = 0; c < 4; c++) od[dt][c] = 0.f;
    float mrow[2] = {-1e30f, -1e30f};
    float lrow[2] = {0.f, 0.f};

    const float* kvb = g_kvl + (long)b * MPOOL * 256 + head * 32;

    for (int j0 = 0; j0 < MPOOL; j0 += 64) {
        __syncthreads();
#pragma unroll
        for (int p = 0; p < 2; p++) {
            const int idx = tid + 256 * p;
            const int r = idx >> 3;
            const int c4 = (idx & 7) * 4;
            const float* row = &kvb[(long)(j0 + r) * 256];
            float4 kf = *(const float4*)&row[c4];
            u32 h0, l0, h1, l1;
            bf16_split2(kf.x, kf.y, h0, l0);
            bf16_split2(kf.z, kf.w, h1, l1);
            *(u32*)&sKhi[r][c4]     = h0;
            *(u32*)&sKhi[r][c4 + 2] = h1;
            *(u32*)&sKlo[r][c4]     = l0;
            *(u32*)&sKlo[r][c4 + 2] = l1;
            float4 vf = *(const float4*)&row[128 + c4];
#pragma unroll
            for (int i = 0; i < 4; i++) {
                float v = (&vf.x)[i];
                __nv_bfloat16 vh = __float2bfloat16(v);
                sVhi[c4 + i][r] = vh;
                sVlo[c4 + i][r] = __float2bfloat16(v - __bfloat162float(vh));
            }
        }
        __syncthreads();

        float s[8][4];
#pragma unroll
        for (int nt = 0; nt < 8; nt++) {
            float c[4] = {0.f, 0.f, 0.f, 0.f};
            const int kv = nt * 8 + g;
#pragma unroll
            for (int kt = 0; kt < 2; kt++) {
                const int kk = kt * 16;
                u32 bh0 = *(const u32*)&sKhi[kv][kk + 2 * tg];
                u32 bh1 = *(const u32*)&sKhi[kv][kk + 8 + 2 * tg];
                u32 bl0 = *(const u32*)&sKlo[kv][kk + 2 * tg];
                u32 bl1 = *(const u32*)&sKlo[kv][kk + 8 + 2 * tg];
                mma_bf16(c, qa_hi[kt], bh0, bh1);
                mma_bf16(c, qa_lo[kt], bh0, bh1);
                mma_bf16(c, qa_hi[kt], bl0, bl1);
            }
            s[nt][0] = c[0]; s[nt][1] = c[1]; s[nt][2] = c[2]; s[nt][3] = c[3];
        }

        float mx0 = s[0][0], mx1 = s[0][2];
#pragma unroll
        for (int nt = 0; nt < 8; nt++) {
            mx0 = fmaxf(mx0, fmaxf(s[nt][0], s[nt][1]));
            mx1 = fmaxf(mx1, fmaxf(s[nt][2], s[nt][3]));
        }
        mx0 = fmaxf(mx0, __shfl_xor_sync(0xffffffffu, mx0, 1));
        mx0 = fmaxf(mx0, __shfl_xor_sync(0xffffffffu, mx0, 2));
        mx1 = fmaxf(mx1, __shfl_xor_sync(0xffffffffu, mx1, 1));
        mx1 = fmaxf(mx1, __shfl_xor_sync(0xffffffffu, mx1, 2));

        const float mn0 = fmaxf(mrow[0], mx0);
        const float mn1 = fmaxf(mrow[1], mx1);
        const float sf0 = __expf(mrow[0] - mn0);
        const float sf1 = __expf(mrow[1] - mn1);
        mrow[0] = mn0; mrow[1] = mn1;
        lrow[0] *= sf0; lrow[1] *= sf1;
#pragma unroll
        for (int dt = 0; dt < 4; dt++) {
            od[dt][0] *= sf0; od[dt][1] *= sf0;
            od[dt][2] *= sf1; od[dt][3] *= sf1;
        }
#pragma unroll
        for (int nt = 0; nt < 8; nt++) {
            s[nt][0] = __expf(s[nt][0] - mn0);
            s[nt][1] = __expf(s[nt][1] - mn0);
            s[nt][2] = __expf(s[nt][2] - mn1);
            s[nt][3] = __expf(s[nt][3] - mn1);
            lrow[0] += s[nt][0] + s[nt][1];
            lrow[1] += s[nt][2] + s[nt][3];
        }

#pragma unroll
        for (int kt2 = 0; kt2 < 4; kt2++) {
            u32 pa_hi[4], pa_lo[4];
            bf16_split2(s[2 * kt2][0],     s[2 * kt2][1],     pa_hi[0], pa_lo[0]);
            bf16_split2(s[2 * kt2][2],     s[2 * kt2][3],     pa_hi[1], pa_lo[1]);
            bf16_split2(s[2 * kt2 + 1][0], s[2 * kt2 + 1][1], pa_hi[2], pa_lo[2]);
            bf16_split2(s[2 * kt2 + 1][2], s[2 * kt2 + 1][3], pa_hi[3], pa_lo[3]);
            const int kv0 = kt2 * 16;
#pragma unroll
            for (int dt = 0; dt < 4; dt++) {
                const int d = dt * 8 + g;
                u32 vb_h0 = *(const u32*)&sVhi[d][kv0 + 2 * tg];
                u32 vb_h1 = *(const u32*)&sVhi[d][kv0 + 8 + 2 * tg];
                u32 vb_l0 = *(const u32*)&sVlo[d][kv0 + 2 * tg];
                u32 vb_l1 = *(const u32*)&sVlo[d][kv0 + 8 + 2 * tg];
                mma_bf16(od[dt], pa_hi, vb_h0, vb_h1);
                mma_bf16(od[dt], pa_lo, vb_h0, vb_h1);
                mma_bf16(od[dt], pa_hi, vb_l0, vb_l1);
            }
        }
    }

    lrow[0] += __shfl_xor_sync(0xffffffffu, lrow[0], 1);
    lrow[0] += __shfl_xor_sync(0xffffffffu, lrow[0], 2);
    lrow[1] += __shfl_xor_sync(0xffffffffu, lrow[1], 1);
    lrow[1] += __shfl_xor_sync(0xffffffffu, lrow[1], 2);
    const float inv0 = 1.0f / lrow[0];
    const float inv1 = 1.0f / lrow[1];

    const long obase = ((long)(b * NTOK + qrow0)) * 128 + head * 32;
#pragma unroll
    for (int dt = 0; dt < 4; dt++) {
        const int col = dt * 8 + 2 * tg;
        u32 h, l;
        bf16_split2(od[dt][0] * inv0, od[dt][1] * inv0, h, l);
        *(u32*)&g_olhi[obase + (long)g * 128 + col] = h;
        *(u32*)&g_ollo[obase + (long)g * 128 + col] = l;
        bf16_split2(od[dt][2] * inv1, od[dt][3] * inv1, h, l);
        *(u32*)&g_olhi[obase + (long)(g + 8) * 128 + col] = h;
        *(u32*)&g_ollo[obase + (long)(g + 8) * 128 + col] = l;
    }
}

// ---------------------------------------------------------------------------
extern "C" void kernel_launch(void* const* d_in, const int* in_sizes, int n_in,
                              void* d_out, int out_size)
{
    const float* x        = (const float*)d_in[0];
    const float* l_q_w    = (const float*)d_in[1];
    const float* l_kv_w   = (const float*)d_in[2];
    const float* l_proj_w = (const float*)d_in[3];
    const float* l_proj_b = (const float*)d_in[4];
    const float* h_qkv_w  = (const float*)d_in[5];
    const float* h_proj_w = (const float*)d_in[6];
    const float* h_proj_b = (const float*)d_in[7];
    float* out = (float*)d_out;

    cudaFuncSetAttribute(gemm_xt_pipe,
                         cudaFuncAttributeMaxDynamicSharedMemorySize, XT_SMEM);
    cudaFuncSetAttribute(gemm_proj_pipe,
                         cudaFuncAttributeMaxDynamicSharedMemorySize, PJ_SMEM);

    float *qkv, *ql, *kvl;
    __nv_bfloat16 *xhi, *xlo, *phi, *plo, *ohhi, *ohlo, *olhi, *ollo;
    cudaGetSymbolAddress((void**)&qkv,  g_qkv);
    cudaGetSymbolAddress((void**)&ql,   g_ql);
    cudaGetSymbolAddress((void**)&kvl,  g_kvl);
    cudaGetSymbolAddress((void**)&xhi,  g_xhi);
    cudaGetSymbolAddress((void**)&xlo,  g_xlo);
    cudaGetSymbolAddress((void**)&phi,  g_phi);
    cudaGetSymbolAddress((void**)&plo,  g_plo);
    cudaGetSymbolAddress((void**)&ohhi, g_ohhi);
    cudaGetSymbolAddress((void**)&ohlo, g_ohlo);
    cudaGetSymbolAddress((void**)&olhi, g_olhi);
    cudaGetSymbolAddress((void**)&ollo, g_ollo);

    // operand conversion
    convert_w<<<224, 256>>>(h_qkv_w, l_q_w, l_kv_w, h_proj_w, l_proj_w);
    convert_x_pool<<<BB * CDIM, 256>>>(x);

    // hifi qkv: x^T @ h_qkv_w -> [b][4096][384] fp32
    gemm_xt_pipe<<<dim3(32, 6, 8), 256, XT_SMEM>>>(
        xhi, xlo, (long)CDIM * NTOK, WOFF_HQKV, qkv, (long)NTOK * 384, NTOK, 384);
    // lofi q: x^T @ l_q_w -> [b][4096][128] fp32
    gemm_xt_pipe<<<dim3(32, 2, 8), 256, XT_SMEM>>>(
        xhi, xlo, (long)CDIM * NTOK, WOFF_LQ, ql, (long)NTOK * 128, NTOK, 128);
    // lofi kv: pooled^T @ l_kv_w -> [b][1024][256] fp32
    gemm_xt_pipe<<<dim3(8, 4, 8), 256, XT_SMEM>>>(
        phi, plo, (long)CDIM * MPOOL, WOFF_LKV, kvl, (long)MPOOL * 256, MPOOL, 256);

    // attention (emit bf16 hi/lo)
    hifi_attn<<<4096, 256>>>();
    lofi_attn_mma<<<dim3(32, 32), 256>>>();

    // projections, fused concat+transpose into output
    gemm_proj_pipe<<<dim3(32, 2, 8), 256, PJ_SMEM>>>(
        ohhi, ohlo, (long)NTOK * 128, WOFF_HPROJ, h_proj_b, out, 0);
    gemm_proj_pipe<<<dim3(32, 2, 8), 256, PJ_SMEM>>>(
        olhi, ollo, (long)NTOK * 128, WOFF_LPROJ, l_proj_b, out, 128);
}